// round 2
// baseline (speedup 1.0000x reference)
#include <cuda_runtime.h>
#include <math.h>

// Problem dims
#define BDIM 32    // batch
#define TDIM 64    // seq len
#define DDIM 32    // n vars / heads
#define HDIM 256   // hidden
#define ZDIM 64    // latent
#define G3   768   // 3*H

// ---- scratch (static device arrays; no allocation) ----
__device__ float g_encGi[BDIM * TDIM * G3];        // [b][t][g]  (6 MB)
__device__ float g_wcomb[DDIM * G3 * DDIM];        // [d][g][i]  (3 MB)
__device__ float g_h0[BDIM * HDIM];                // [b][u]

__device__ __forceinline__ float sigmoidf_(float x) {
    return __fdividef(1.0f, 1.0f + __expf(-x));
}
__device__ __forceinline__ float tanhf_(float x) {
    // tanh(x) = 1 - 2/(e^{2x}+1); exact limits at +-inf via IEEE
    return 1.0f - __fdividef(2.0f, __expf(2.0f * x) + 1.0f);
}

// ============================================================
// Prep 1: encoder input gates  gi[b,t,g] = x_past[b,t,:] . Wih[g,:] + bih[g]
// grid = B*T blocks, 256 threads
// ============================================================
__global__ __launch_bounds__(256) void prep_encgi(
    const float* __restrict__ xp, const float* __restrict__ Wih,
    const float* __restrict__ bih)
{
    __shared__ float xs[DDIM];
    int bt = blockIdx.x;
    int tid = threadIdx.x;
    if (tid < DDIM) xs[tid] = xp[bt * DDIM + tid];
    __syncthreads();
#pragma unroll
    for (int r = 0; r < 3; r++) {
        int g = tid + r * HDIM;
        const float4* w = (const float4*)(Wih + g * DDIM);
        float acc = bih[g];
#pragma unroll
        for (int i4 = 0; i4 < DDIM / 4; i4++) {
            float4 wv = w[i4];
            acc += wv.x * xs[i4 * 4 + 0] + wv.y * xs[i4 * 4 + 1] +
                   wv.z * xs[i4 * 4 + 2] + wv.w * xs[i4 * 4 + 3];
        }
        g_encGi[bt * G3 + g] = acc;
    }
}

// ============================================================
// Prep 2: combined input matrix  W_comb[d][g][i] = sum_h Win[d][i][h]*Wih[d][g][h]
// grid = 32 heads * 96 g-blocks (8 g each), 256 threads
// ============================================================
__global__ __launch_bounds__(256) void prep_wcomb(
    const float* __restrict__ Win, const float* __restrict__ Wih)
{
    int d  = blockIdx.x / 96;
    int gb = blockIdx.x % 96;
    __shared__ float win_s[DDIM * HDIM]; // [i][h] 32 KB
    __shared__ float wih_s[8 * HDIM];    // [gg][h] 8 KB
    int tid = threadIdx.x;
    const float* winp = Win + d * DDIM * HDIM;
    for (int idx = tid; idx < DDIM * HDIM; idx += 256) win_s[idx] = winp[idx];
    const float* wihp = Wih + (d * G3 + gb * 8) * HDIM;
    for (int idx = tid; idx < 8 * HDIM; idx += 256) wih_s[idx] = wihp[idx];
    __syncthreads();
    int gg = tid & 7, i = tid >> 3;
    int rot = tid & (HDIM - 1);
    float acc = 0.0f;
#pragma unroll 8
    for (int h = 0; h < HDIM; h++) {
        int hh = (h + rot) & (HDIM - 1); // lane-rotated for conflict-free LDS
        acc += win_s[i * HDIM + hh] * wih_s[gg * HDIM + hh];
    }
    g_wcomb[(d * G3 + gb * 8 + gg) * DDIM + i] = acc;
}

// ============================================================
// Encoder GRU + VAE head: one CTA per batch element (32 CTAs, 256 threads)
// thread u owns hidden unit u (gate rows u, u+256, u+512)
// ============================================================
__global__ __launch_bounds__(256) void enc_gru(
    const float* __restrict__ Whh,   const float* __restrict__ bhh,
    const float* __restrict__ mu_w,  const float* __restrict__ mu_b,
    const float* __restrict__ ls_w,  const float* __restrict__ ls_b,
    const float* __restrict__ refc_w, const float* __restrict__ refc_b,
    const float* __restrict__ eps,   float* __restrict__ out)
{
    int b = blockIdx.x;
    int u = threadIdx.x;
    __shared__ __align__(16) float h_s[HDIM];
    __shared__ float zv[ZDIM];

    h_s[u] = 0.0f;
    float bhr = bhh[u], bhz = bhh[u + HDIM], bhn = bhh[u + 2 * HDIM];
    const float4* Wr = (const float4*)(Whh + (size_t)u * HDIM);
    const float4* Wz = (const float4*)(Whh + (size_t)(u + HDIM) * HDIM);
    const float4* Wn = (const float4*)(Whh + (size_t)(u + 2 * HDIM) * HDIM);
    __syncthreads();

    for (int t = 0; t < TDIM; t++) {
        const float* gi = g_encGi + (b * TDIM + t) * G3;
        float aR  = gi[u] + bhr;
        float aZ  = gi[u + HDIM] + bhz;
        float aNi = gi[u + 2 * HDIM];
        float aNh = bhn;
        const float4* h4 = (const float4*)h_s;
#pragma unroll 4
        for (int k4 = 0; k4 < HDIM / 4; k4++) {
            float4 hv = h4[k4];
            float4 wr = Wr[k4], wz = Wz[k4], wn = Wn[k4];
            aR  += wr.x * hv.x + wr.y * hv.y + wr.z * hv.z + wr.w * hv.w;
            aZ  += wz.x * hv.x + wz.y * hv.y + wz.z * hv.z + wz.w * hv.w;
            aNh += wn.x * hv.x + wn.y * hv.y + wn.z * hv.z + wn.w * hv.w;
        }
        float r  = sigmoidf_(aR);
        float zz = sigmoidf_(aZ);
        float n  = tanhf_(aNi + r * aNh);
        float hnew = (1.0f - zz) * n + zz * h_s[u];
        __syncthreads();
        h_s[u] = hnew;
        __syncthreads();
    }

    // VAE head
    if (u < ZDIM) {
        const float* mw = mu_w + u * HDIM;
        const float* lw = ls_w + u * HDIM;
        float am = mu_b[u], al = ls_b[u];
#pragma unroll 8
        for (int k = 0; k < HDIM; k++) { am += mw[k] * h_s[k]; al += lw[k] * h_s[k]; }
        out[BDIM * TDIM * DDIM + b * ZDIM + u] = am;                 // mu
        out[BDIM * TDIM * DDIM + BDIM * ZDIM + b * ZDIM + u] = al;   // logsigma
        zv[u] = am + eps[b * ZDIM + u] * __expf(al);
    }
    __syncthreads();
    // h0 = tanh(refc_w @ z + refc_b)
    {
        float acc = refc_b[u];
        const float* rw = refc_w + u * ZDIM;
#pragma unroll 8
        for (int j = 0; j < ZDIM; j++) acc += rw[j] * zv[j];
        g_h0[b * HDIM + u] = tanhf_(acc);
    }
}

// ============================================================
// Decoder: 128 CTAs = 32 heads x 4 batch-slices of 8, 256 threads.
// thread u owns hidden unit u across its 8 batches. Zero inter-CTA sync.
// ============================================================
__global__ __launch_bounds__(256) void dec_gru(
    const float* __restrict__ xp, const float* __restrict__ xc,
    const float* __restrict__ Whh_all, const float* __restrict__ bih_all,
    const float* __restrict__ bhh_all, const float* __restrict__ fcw_all,
    const float* __restrict__ fcb_all, float* __restrict__ out)
{
    int d  = blockIdx.x >> 2;
    int b0 = (blockIdx.x & 3) * 8;
    int tid = threadIdx.x;
    int u = tid;

    __shared__ __align__(16) float h_s[HDIM][8];
    __shared__ __align__(16) float din_s[DDIM][8];
    __shared__ float wsum[8][8];

    const float* Whh = Whh_all + (size_t)d * G3 * HDIM;
    const float* bih = bih_all + d * G3;
    const float* bhh = bhh_all + d * G3;
    float fcw = fcw_all[d * HDIM + u];
    float fcb = fcb_all[d];

    const float4* Wr = (const float4*)(Whh + (size_t)u * HDIM);
    const float4* Wz = (const float4*)(Whh + (size_t)(u + HDIM) * HDIM);
    const float4* Wn = (const float4*)(Whh + (size_t)(u + 2 * HDIM) * HDIM);
    const float* Cw = g_wcomb + (size_t)d * G3 * DDIM;
    const float4* Cr = (const float4*)(Cw + (size_t)u * DDIM);
    const float4* Cz = (const float4*)(Cw + (size_t)(u + HDIM) * DDIM);
    const float4* Cn = (const float4*)(Cw + (size_t)(u + 2 * HDIM) * DDIM);

    float br  = bih[u] + bhh[u];
    float bz  = bih[u + HDIM] + bhh[u + HDIM];
    float bni = bih[u + 2 * HDIM];
    float bnh = bhh[u + 2 * HDIM];

    // init h from h0, stage din for t=0 (x_past[:, -1, :])
    for (int j = tid; j < HDIM * 8; j += 256) {
        int uu = j >> 3, bb = j & 7;
        h_s[uu][bb] = g_h0[(b0 + bb) * HDIM + uu];
    }
    {
        int k = tid >> 3, bb = tid & 7;
        din_s[k][bb] = xp[(b0 + bb) * TDIM * DDIM + (TDIM - 1) * DDIM + k];
    }
    __syncthreads();

    for (int t = 0; t < TDIM; t++) {
        float aR[8], aZ[8], aNi[8], aNh[8];
#pragma unroll
        for (int bb = 0; bb < 8; bb++) { aR[bb] = br; aZ[bb] = bz; aNi[bb] = bni; aNh[bb] = bnh; }

        const float4* h4 = (const float4*)&h_s[0][0];
#pragma unroll 2
        for (int k4 = 0; k4 < HDIM / 4; k4++) {
            float4 wr = Wr[k4], wz = Wz[k4], wn = Wn[k4];
            float wrk[4] = {wr.x, wr.y, wr.z, wr.w};
            float wzk[4] = {wz.x, wz.y, wz.z, wz.w};
            float wnk[4] = {wn.x, wn.y, wn.z, wn.w};
#pragma unroll
            for (int kk = 0; kk < 4; kk++) {
                float4 p = h4[(k4 * 4 + kk) * 2];
                float4 q = h4[(k4 * 4 + kk) * 2 + 1];
                float hv[8] = {p.x, p.y, p.z, p.w, q.x, q.y, q.z, q.w};
#pragma unroll
                for (int bb = 0; bb < 8; bb++) {
                    aR[bb]  += wrk[kk] * hv[bb];
                    aZ[bb]  += wzk[kk] * hv[bb];
                    aNh[bb] += wnk[kk] * hv[bb];
                }
            }
        }
        const float4* d4 = (const float4*)&din_s[0][0];
#pragma unroll
        for (int k4 = 0; k4 < DDIM / 4; k4++) {
            float4 cr = Cr[k4], cz = Cz[k4], cn = Cn[k4];
            float crk[4] = {cr.x, cr.y, cr.z, cr.w};
            float czk[4] = {cz.x, cz.y, cz.z, cz.w};
            float cnk[4] = {cn.x, cn.y, cn.z, cn.w};
#pragma unroll
            for (int kk = 0; kk < 4; kk++) {
                float4 p = d4[(k4 * 4 + kk) * 2];
                float4 q = d4[(k4 * 4 + kk) * 2 + 1];
                float dv[8] = {p.x, p.y, p.z, p.w, q.x, q.y, q.z, q.w};
#pragma unroll
                for (int bb = 0; bb < 8; bb++) {
                    aR[bb]  += crk[kk] * dv[bb];
                    aZ[bb]  += czk[kk] * dv[bb];
                    aNi[bb] += cnk[kk] * dv[bb];
                }
            }
        }

        float hn[8], pr[8];
#pragma unroll
        for (int bb = 0; bb < 8; bb++) {
            float r  = sigmoidf_(aR[bb]);
            float zz = sigmoidf_(aZ[bb]);
            float n  = tanhf_(aNi[bb] + r * aNh[bb]);
            float hold = h_s[u][bb];
            hn[bb] = (1.0f - zz) * n + zz * hold;
            pr[bb] = fcw * hn[bb];
        }
        // fc: reduce fcw*h over 256 units
#pragma unroll
        for (int off = 16; off; off >>= 1) {
#pragma unroll
            for (int bb = 0; bb < 8; bb++)
                pr[bb] += __shfl_xor_sync(0xffffffff, pr[bb], off);
        }
        if ((tid & 31) == 0) {
            int w = tid >> 5;
#pragma unroll
            for (int bb = 0; bb < 8; bb++) wsum[w][bb] = pr[bb];
        }
        __syncthreads();   // all reads of h_s/din_s done; wsum visible

        *(float4*)&h_s[u][0] = make_float4(hn[0], hn[1], hn[2], hn[3]);
        *(float4*)&h_s[u][4] = make_float4(hn[4], hn[5], hn[6], hn[7]);
        if (t + 1 < TDIM) {
            int k = tid >> 3, bb = tid & 7;
            din_s[k][bb] = xc[(b0 + bb) * TDIM * DDIM + t * DDIM + k];
        }
        if (tid < 8) {
            float s = fcb;
#pragma unroll
            for (int w = 0; w < 8; w++) s += wsum[w][tid];
            out[(b0 + tid) * TDIM * DDIM + t * DDIM + d] = s;
        }
        __syncthreads();   // h/din writes visible before next step's reads
    }
}

// ============================================================
// launch
// ============================================================
extern "C" void kernel_launch(void* const* d_in, const int* in_sizes, int n_in,
                              void* d_out, int out_size)
{
    const float* x_past   = (const float*)d_in[0];
    const float* x_current= (const float*)d_in[1];
    const float* eps      = (const float*)d_in[2];
    const float* enc_Wih  = (const float*)d_in[3];
    const float* enc_bih  = (const float*)d_in[4];
    const float* enc_Whh  = (const float*)d_in[5];
    const float* enc_bhh  = (const float*)d_in[6];
    const float* enc_mu_w = (const float*)d_in[7];
    const float* enc_mu_b = (const float*)d_in[8];
    const float* enc_ls_w = (const float*)d_in[9];
    const float* enc_ls_b = (const float*)d_in[10];
    const float* refc_w   = (const float*)d_in[11];
    const float* refc_b   = (const float*)d_in[12];
    const float* Win      = (const float*)d_in[13];
    const float* h_Wih    = (const float*)d_in[14];
    const float* h_bih    = (const float*)d_in[15];
    const float* h_Whh    = (const float*)d_in[16];
    const float* h_bhh    = (const float*)d_in[17];
    const float* fc_w     = (const float*)d_in[18];
    const float* fc_b     = (const float*)d_in[19];
    float* out = (float*)d_out;

    prep_encgi<<<BDIM * TDIM, 256>>>(x_past, enc_Wih, enc_bih);
    prep_wcomb<<<DDIM * 96, 256>>>(Win, h_Wih);
    enc_gru<<<BDIM, 256>>>(enc_Whh, enc_bhh, enc_mu_w, enc_mu_b,
                           enc_ls_w, enc_ls_b, refc_w, refc_b, eps, out);
    dec_gru<<<DDIM * 4, 256>>>(x_past, x_current, h_Whh, h_bih, h_bhh,
                               fc_w, fc_b, out);
}

// round 3
// speedup vs baseline: 1.0006x; 1.0006x over previous
#include <cuda_runtime.h>
#include <math.h>

// Problem dims
#define BDIM 32    // batch
#define TDIM 64    // seq len
#define DDIM 32    // n vars / heads
#define HDIM 256   // hidden
#define ZDIM 64    // latent
#define G3   768   // 3*H

// ---- scratch (static device arrays; no allocation) ----
__device__ float g_encGi[BDIM * TDIM * G3];        // [b][t][g]  (6 MB)
__device__ float g_wcomb[DDIM * G3 * DDIM];        // [d][g][i]  (3 MB)
__device__ float g_h0[BDIM * HDIM];                // [b][u]

__device__ __forceinline__ float sigmoidf_(float x) {
    return __fdividef(1.0f, 1.0f + __expf(-x));
}
__device__ __forceinline__ float tanhf_(float x) {
    // tanh(x) = 1 - 2/(e^{2x}+1); exact limits at +-inf via IEEE
    return 1.0f - __fdividef(2.0f, __expf(2.0f * x) + 1.0f);
}

// ============================================================
// Prep 1: encoder input gates  gi[b,t,g] = x_past[b,t,:] . Wih[g,:] + bih[g]
// grid = B*T blocks, 256 threads
// ============================================================
__global__ __launch_bounds__(256) void prep_encgi(
    const float* __restrict__ xp, const float* __restrict__ Wih,
    const float* __restrict__ bih)
{
    __shared__ float xs[DDIM];
    int bt = blockIdx.x;
    int tid = threadIdx.x;
    if (tid < DDIM) xs[tid] = xp[bt * DDIM + tid];
    __syncthreads();
#pragma unroll
    for (int r = 0; r < 3; r++) {
        int g = tid + r * HDIM;
        const float4* w = (const float4*)(Wih + g * DDIM);
        float acc = bih[g];
#pragma unroll
        for (int i4 = 0; i4 < DDIM / 4; i4++) {
            float4 wv = w[i4];
            acc += wv.x * xs[i4 * 4 + 0] + wv.y * xs[i4 * 4 + 1] +
                   wv.z * xs[i4 * 4 + 2] + wv.w * xs[i4 * 4 + 3];
        }
        g_encGi[bt * G3 + g] = acc;
    }
}

// ============================================================
// Prep 2: combined input matrix  W_comb[d][g][i] = sum_h Win[d][i][h]*Wih[d][g][h]
// grid = 32 heads * 96 g-blocks (8 g each), 256 threads
// ============================================================
__global__ __launch_bounds__(256) void prep_wcomb(
    const float* __restrict__ Win, const float* __restrict__ Wih)
{
    int d  = blockIdx.x / 96;
    int gb = blockIdx.x % 96;
    __shared__ float win_s[DDIM * HDIM]; // [i][h] 32 KB
    __shared__ float wih_s[8 * HDIM];    // [gg][h] 8 KB
    int tid = threadIdx.x;
    const float* winp = Win + d * DDIM * HDIM;
    for (int idx = tid; idx < DDIM * HDIM; idx += 256) win_s[idx] = winp[idx];
    const float* wihp = Wih + (d * G3 + gb * 8) * HDIM;
    for (int idx = tid; idx < 8 * HDIM; idx += 256) wih_s[idx] = wihp[idx];
    __syncthreads();
    int gg = tid & 7, i = tid >> 3;
    int rot = tid & (HDIM - 1);
    float acc = 0.0f;
#pragma unroll 8
    for (int h = 0; h < HDIM; h++) {
        int hh = (h + rot) & (HDIM - 1); // lane-rotated for conflict-free LDS
        acc += win_s[i * HDIM + hh] * wih_s[gg * HDIM + hh];
    }
    g_wcomb[(d * G3 + gb * 8 + gg) * DDIM + i] = acc;
}

// ============================================================
// Encoder GRU + VAE head: one CTA per batch element (32 CTAs, 256 threads)
// thread u owns hidden unit u (gate rows u, u+256, u+512)
// ============================================================
__global__ __launch_bounds__(256) void enc_gru(
    const float* __restrict__ Whh,   const float* __restrict__ bhh,
    const float* __restrict__ mu_w,  const float* __restrict__ mu_b,
    const float* __restrict__ ls_w,  const float* __restrict__ ls_b,
    const float* __restrict__ refc_w, const float* __restrict__ refc_b,
    const float* __restrict__ eps,   float* __restrict__ out)
{
    int b = blockIdx.x;
    int u = threadIdx.x;
    __shared__ __align__(16) float h_s[HDIM];
    __shared__ float zv[ZDIM];

    h_s[u] = 0.0f;
    float bhr = bhh[u], bhz = bhh[u + HDIM], bhn = bhh[u + 2 * HDIM];
    const float4* Wr = (const float4*)(Whh + (size_t)u * HDIM);
    const float4* Wz = (const float4*)(Whh + (size_t)(u + HDIM) * HDIM);
    const float4* Wn = (const float4*)(Whh + (size_t)(u + 2 * HDIM) * HDIM);
    __syncthreads();

    for (int t = 0; t < TDIM; t++) {
        const float* gi = g_encGi + (b * TDIM + t) * G3;
        float aR  = gi[u] + bhr;
        float aZ  = gi[u + HDIM] + bhz;
        float aNi = gi[u + 2 * HDIM];
        float aNh = bhn;
        const float4* h4 = (const float4*)h_s;
#pragma unroll 4
        for (int k4 = 0; k4 < HDIM / 4; k4++) {
            float4 hv = h4[k4];
            float4 wr = Wr[k4], wz = Wz[k4], wn = Wn[k4];
            aR  += wr.x * hv.x + wr.y * hv.y + wr.z * hv.z + wr.w * hv.w;
            aZ  += wz.x * hv.x + wz.y * hv.y + wz.z * hv.z + wz.w * hv.w;
            aNh += wn.x * hv.x + wn.y * hv.y + wn.z * hv.z + wn.w * hv.w;
        }
        float r  = sigmoidf_(aR);
        float zz = sigmoidf_(aZ);
        float n  = tanhf_(aNi + r * aNh);
        float hnew = (1.0f - zz) * n + zz * h_s[u];
        __syncthreads();
        h_s[u] = hnew;
        __syncthreads();
    }

    // VAE head
    if (u < ZDIM) {
        const float* mw = mu_w + u * HDIM;
        const float* lw = ls_w + u * HDIM;
        float am = mu_b[u], al = ls_b[u];
#pragma unroll 8
        for (int k = 0; k < HDIM; k++) { am += mw[k] * h_s[k]; al += lw[k] * h_s[k]; }
        out[BDIM * TDIM * DDIM + b * ZDIM + u] = am;                 // mu
        out[BDIM * TDIM * DDIM + BDIM * ZDIM + b * ZDIM + u] = al;   // logsigma
        zv[u] = am + eps[b * ZDIM + u] * __expf(al);
    }
    __syncthreads();
    // h0 = tanh(refc_w @ z + refc_b)
    {
        float acc = refc_b[u];
        const float* rw = refc_w + u * ZDIM;
#pragma unroll 8
        for (int j = 0; j < ZDIM; j++) acc += rw[j] * zv[j];
        g_h0[b * HDIM + u] = tanhf_(acc);
    }
}

// ============================================================
// Decoder: 128 CTAs = 32 heads x 4 batch-slices of 8, 256 threads.
// thread u owns hidden unit u across its 8 batches. Zero inter-CTA sync.
// ============================================================
__global__ __launch_bounds__(256) void dec_gru(
    const float* __restrict__ xp, const float* __restrict__ xc,
    const float* __restrict__ Whh_all, const float* __restrict__ bih_all,
    const float* __restrict__ bhh_all, const float* __restrict__ fcw_all,
    const float* __restrict__ fcb_all, float* __restrict__ out)
{
    int d  = blockIdx.x >> 2;
    int b0 = (blockIdx.x & 3) * 8;
    int tid = threadIdx.x;
    int u = tid;

    __shared__ __align__(16) float h_s[HDIM][8];
    __shared__ __align__(16) float din_s[DDIM][8];
    __shared__ float wsum[8][8];

    const float* Whh = Whh_all + (size_t)d * G3 * HDIM;
    const float* bih = bih_all + d * G3;
    const float* bhh = bhh_all + d * G3;
    float fcw = fcw_all[d * HDIM + u];
    float fcb = fcb_all[d];

    const float4* Wr = (const float4*)(Whh + (size_t)u * HDIM);
    const float4* Wz = (const float4*)(Whh + (size_t)(u + HDIM) * HDIM);
    const float4* Wn = (const float4*)(Whh + (size_t)(u + 2 * HDIM) * HDIM);
    const float* Cw = g_wcomb + (size_t)d * G3 * DDIM;
    const float4* Cr = (const float4*)(Cw + (size_t)u * DDIM);
    const float4* Cz = (const float4*)(Cw + (size_t)(u + HDIM) * DDIM);
    const float4* Cn = (const float4*)(Cw + (size_t)(u + 2 * HDIM) * DDIM);

    float br  = bih[u] + bhh[u];
    float bz  = bih[u + HDIM] + bhh[u + HDIM];
    float bni = bih[u + 2 * HDIM];
    float bnh = bhh[u + 2 * HDIM];

    // init h from h0, stage din for t=0 (x_past[:, -1, :])
    for (int j = tid; j < HDIM * 8; j += 256) {
        int uu = j >> 3, bb = j & 7;
        h_s[uu][bb] = g_h0[(b0 + bb) * HDIM + uu];
    }
    {
        int k = tid >> 3, bb = tid & 7;
        din_s[k][bb] = xp[(b0 + bb) * TDIM * DDIM + (TDIM - 1) * DDIM + k];
    }
    __syncthreads();

    for (int t = 0; t < TDIM; t++) {
        float aR[8], aZ[8], aNi[8], aNh[8];
#pragma unroll
        for (int bb = 0; bb < 8; bb++) { aR[bb] = br; aZ[bb] = bz; aNi[bb] = bni; aNh[bb] = bnh; }

        const float4* h4 = (const float4*)&h_s[0][0];
#pragma unroll 2
        for (int k4 = 0; k4 < HDIM / 4; k4++) {
            float4 wr = Wr[k4], wz = Wz[k4], wn = Wn[k4];
            float wrk[4] = {wr.x, wr.y, wr.z, wr.w};
            float wzk[4] = {wz.x, wz.y, wz.z, wz.w};
            float wnk[4] = {wn.x, wn.y, wn.z, wn.w};
#pragma unroll
            for (int kk = 0; kk < 4; kk++) {
                float4 p = h4[(k4 * 4 + kk) * 2];
                float4 q = h4[(k4 * 4 + kk) * 2 + 1];
                float hv[8] = {p.x, p.y, p.z, p.w, q.x, q.y, q.z, q.w};
#pragma unroll
                for (int bb = 0; bb < 8; bb++) {
                    aR[bb]  += wrk[kk] * hv[bb];
                    aZ[bb]  += wzk[kk] * hv[bb];
                    aNh[bb] += wnk[kk] * hv[bb];
                }
            }
        }
        const float4* d4 = (const float4*)&din_s[0][0];
#pragma unroll
        for (int k4 = 0; k4 < DDIM / 4; k4++) {
            float4 cr = Cr[k4], cz = Cz[k4], cn = Cn[k4];
            float crk[4] = {cr.x, cr.y, cr.z, cr.w};
            float czk[4] = {cz.x, cz.y, cz.z, cz.w};
            float cnk[4] = {cn.x, cn.y, cn.z, cn.w};
#pragma unroll
            for (int kk = 0; kk < 4; kk++) {
                float4 p = d4[(k4 * 4 + kk) * 2];
                float4 q = d4[(k4 * 4 + kk) * 2 + 1];
                float dv[8] = {p.x, p.y, p.z, p.w, q.x, q.y, q.z, q.w};
#pragma unroll
                for (int bb = 0; bb < 8; bb++) {
                    aR[bb]  += crk[kk] * dv[bb];
                    aZ[bb]  += czk[kk] * dv[bb];
                    aNi[bb] += cnk[kk] * dv[bb];
                }
            }
        }

        float hn[8], pr[8];
#pragma unroll
        for (int bb = 0; bb < 8; bb++) {
            float r  = sigmoidf_(aR[bb]);
            float zz = sigmoidf_(aZ[bb]);
            float n  = tanhf_(aNi[bb] + r * aNh[bb]);
            float hold = h_s[u][bb];
            hn[bb] = (1.0f - zz) * n + zz * hold;
            pr[bb] = fcw * hn[bb];
        }
        // fc: reduce fcw*h over 256 units
#pragma unroll
        for (int off = 16; off; off >>= 1) {
#pragma unroll
            for (int bb = 0; bb < 8; bb++)
                pr[bb] += __shfl_xor_sync(0xffffffff, pr[bb], off);
        }
        if ((tid & 31) == 0) {
            int w = tid >> 5;
#pragma unroll
            for (int bb = 0; bb < 8; bb++) wsum[w][bb] = pr[bb];
        }
        __syncthreads();   // all reads of h_s/din_s done; wsum visible

        *(float4*)&h_s[u][0] = make_float4(hn[0], hn[1], hn[2], hn[3]);
        *(float4*)&h_s[u][4] = make_float4(hn[4], hn[5], hn[6], hn[7]);
        if (t + 1 < TDIM) {
            int k = tid >> 3, bb = tid & 7;
            din_s[k][bb] = xc[(b0 + bb) * TDIM * DDIM + t * DDIM + k];
        }
        if (tid < 8) {
            float s = fcb;
#pragma unroll
            for (int w = 0; w < 8; w++) s += wsum[w][tid];
            out[(b0 + tid) * TDIM * DDIM + t * DDIM + d] = s;
        }
        __syncthreads();   // h/din writes visible before next step's reads
    }
}

// ============================================================
// launch
// ============================================================
extern "C" void kernel_launch(void* const* d_in, const int* in_sizes, int n_in,
                              void* d_out, int out_size)
{
    const float* x_past   = (const float*)d_in[0];
    const float* x_current= (const float*)d_in[1];
    const float* eps      = (const float*)d_in[2];
    const float* enc_Wih  = (const float*)d_in[3];
    const float* enc_bih  = (const float*)d_in[4];
    const float* enc_Whh  = (const float*)d_in[5];
    const float* enc_bhh  = (const float*)d_in[6];
    const float* enc_mu_w = (const float*)d_in[7];
    const float* enc_mu_b = (const float*)d_in[8];
    const float* enc_ls_w = (const float*)d_in[9];
    const float* enc_ls_b = (const float*)d_in[10];
    const float* refc_w   = (const float*)d_in[11];
    const float* refc_b   = (const float*)d_in[12];
    const float* Win      = (const float*)d_in[13];
    const float* h_Wih    = (const float*)d_in[14];
    const float* h_bih    = (const float*)d_in[15];
    const float* h_Whh    = (const float*)d_in[16];
    const float* h_bhh    = (const float*)d_in[17];
    const float* fc_w     = (const float*)d_in[18];
    const float* fc_b     = (const float*)d_in[19];
    float* out = (float*)d_out;

    prep_encgi<<<BDIM * TDIM, 256>>>(x_past, enc_Wih, enc_bih);
    prep_wcomb<<<DDIM * 96, 256>>>(Win, h_Wih);
    enc_gru<<<BDIM, 256>>>(enc_Whh, enc_bhh, enc_mu_w, enc_mu_b,
                           enc_ls_w, enc_ls_b, refc_w, refc_b, eps, out);
    dec_gru<<<DDIM * 4, 256>>>(x_past, x_current, h_Whh, h_bih, h_bhh,
                               fc_w, fc_b, out);
}